// round 4
// baseline (speedup 1.0000x reference)
#include <cuda_runtime.h>
#include <math.h>
#include <stdint.h>

#define NLR  50000
#define EMBD 128
#define ENUM 800000
#define EPT  256   // edges per block in edge kernel

// ---------------- device scratch (no allocations allowed) ----------------
__device__ float g_logits[(size_t)ENUM * 4];
__device__ float g_xl[(size_t)NLR * EMBD];
__device__ float g_xr[(size_t)NLR * EMBD];
__device__ float g_ln[(size_t)NLR * EMBD];
__device__ float g_h1[(size_t)NLR * EMBD];
__device__ int   g_cnt[NLR];
__device__ int   g_off[NLR + 1];
__device__ int   g_cur[NLR];
__device__ int   g_elist[ENUM];

// ---------------- helpers ----------------
__device__ __forceinline__ uint32_t f2tf(float f) {
    uint32_t u;
    asm("cvt.rna.tf32.f32 %0, %1;" : "=r"(u) : "f"(f));
    return u;
}

__device__ __forceinline__ void mma8(float c[4], const uint32_t a[4], const uint32_t b[2]) {
    asm volatile(
        "mma.sync.aligned.m16n8k8.row.col.f32.tf32.tf32.f32 "
        "{%0,%1,%2,%3},{%4,%5,%6,%7},{%8,%9},{%0,%1,%2,%3};\n"
        : "+f"(c[0]), "+f"(c[1]), "+f"(c[2]), "+f"(c[3])
        : "r"(a[0]), "r"(a[1]), "r"(a[2]), "r"(a[3]), "r"(b[0]), "r"(b[1]));
}

// =================================================================
// Generic tf32 GEMM: C[M,128] = act( A1[M,K1]@B1 + A2[M,K2]@B2 + bias )
// Block tile 128x128, 8 warps in 4x2 grid (warp tile 32x64), K chunks of 32.
// =================================================================
__global__ __launch_bounds__(256) void gemm128(
    const float* __restrict__ A1, const float* __restrict__ B1, int K1,
    const float* __restrict__ A2, const float* __restrict__ B2, int K2,
    const float* __restrict__ bias, float* __restrict__ C, int M, int doRelu)
{
    __shared__ uint32_t As[128][36];
    __shared__ uint32_t Bs[32][136];
    __shared__ float    bias_s[128];

    const int tid = threadIdx.x;
    const int m0  = blockIdx.x * 128;
    if (tid < 128) bias_s[tid] = bias[tid];

    const int warp = tid >> 5, lane = tid & 31;
    const int wm = warp & 3, wn = warp >> 2;
    const int grp = lane >> 2, tg = lane & 3;

    float acc[2][8][4];
#pragma unroll
    for (int a = 0; a < 2; a++)
#pragma unroll
        for (int b = 0; b < 8; b++)
#pragma unroll
            for (int k = 0; k < 4; k++) acc[a][b][k] = 0.f;

    const int nch1 = K1 >> 5;
    const int nch  = nch1 + (K2 >> 5);

    for (int c = 0; c < nch; c++) {
        const float *A, *B; int K, kk;
        if (c < nch1) { A = A1; B = B1; K = K1; kk = c * 32; }
        else          { A = A2; B = B2; K = K2; kk = (c - nch1) * 32; }
        __syncthreads();
#pragma unroll
        for (int i = 0; i < 4; i++) {
            int slot = tid + i * 256;
            int r = slot >> 3, c4 = slot & 7;
            int grow = m0 + r;
            float4 a = (grow < M) ? *(const float4*)(A + (size_t)grow * K + kk + c4 * 4)
                                  : make_float4(0.f, 0.f, 0.f, 0.f);
            *(uint4*)&As[r][c4 * 4] = make_uint4(f2tf(a.x), f2tf(a.y), f2tf(a.z), f2tf(a.w));
            int rb = slot >> 5, cb = slot & 31;
            float4 b = *(const float4*)(B + (size_t)(kk + rb) * 128 + cb * 4);
            *(uint4*)&Bs[rb][cb * 4] = make_uint4(f2tf(b.x), f2tf(b.y), f2tf(b.z), f2tf(b.w));
        }
        __syncthreads();

#pragma unroll
        for (int ks = 0; ks < 4; ks++) {
            const int kb = ks * 8;
            uint32_t af[2][4];
#pragma unroll
            for (int mt = 0; mt < 2; mt++) {
                int r0 = wm * 32 + mt * 16 + grp;
                af[mt][0] = As[r0][kb + tg];     af[mt][1] = As[r0 + 8][kb + tg];
                af[mt][2] = As[r0][kb + tg + 4]; af[mt][3] = As[r0 + 8][kb + tg + 4];
            }
#pragma unroll
            for (int nt = 0; nt < 8; nt++) {
                int cc = wn * 64 + nt * 8 + grp;
                uint32_t bf[2];
                bf[0] = Bs[kb + tg][cc];
                bf[1] = Bs[kb + tg + 4][cc];
#pragma unroll
                for (int mt = 0; mt < 2; mt++) mma8(acc[mt][nt], af[mt], bf);
            }
        }
    }

#pragma unroll
    for (int mt = 0; mt < 2; mt++) {
#pragma unroll
        for (int half = 0; half < 2; half++) {
            int grow = m0 + wm * 32 + mt * 16 + half * 8 + grp;
            if (grow < M) {
#pragma unroll
                for (int nt = 0; nt < 8; nt++) {
                    int cc = wn * 64 + nt * 8 + tg * 2;
                    float v0 = acc[mt][nt][half * 2 + 0] + bias_s[cc];
                    float v1 = acc[mt][nt][half * 2 + 1] + bias_s[cc + 1];
                    if (doRelu) { v0 = fmaxf(v0, 0.f); v1 = fmaxf(v1, 0.f); }
                    float2 o; o.x = v0; o.y = v1;
                    *(float2*)(C + (size_t)grow * 128 + cc) = o;
                }
            }
        }
    }
}

// =================================================================
// Fused edge kernel: eproj = EF @ W_e (tf32 mma, never materialized),
// z = leakyrelu(eproj + x_l[src] + x_r[dst], 0.2),
// logits[e,h] = z_h . att_h  -> g_logits[E][4]
// W_e stationary in smem; 2 M-tiles of 128 edges per block;
// A chunks double-buffered with register staging.
// =================================================================
#define SMEM_WS   (128 * 136 * 4)              // 69632
#define SMEM_AS   (2 * 128 * 36 * 4)           // 36864
#define SMEM_EDGE (SMEM_WS + SMEM_AS + EPT * 8 + 512)

__global__ __launch_bounds__(256) void edge_logits_kernel(
    const float* __restrict__ EF, const float* __restrict__ We,
    const int* __restrict__ src, const int* __restrict__ dst,
    const float* __restrict__ att)
{
    extern __shared__ char smem_raw[];
    uint32_t (*Ws)[136]     = (uint32_t(*)[136])(smem_raw);
    uint32_t (*As)[128][36] = (uint32_t(*)[128][36])(smem_raw + SMEM_WS);
    int*   src_s = (int*)(smem_raw + SMEM_WS + SMEM_AS);
    int*   dst_s = src_s + EPT;
    float* att_s = (float*)(dst_s + EPT);

    const int tid = threadIdx.x;
    const int e0  = blockIdx.x * EPT;

    // stationary W_e (tf32) in smem
#pragma unroll
    for (int i = 0; i < 16; i++) {
        int slot = tid + i * 256;
        int r = slot >> 5, c4 = slot & 31;
        float4 w = *(const float4*)(We + (size_t)r * 128 + c4 * 4);
        *(uint4*)&Ws[r][c4 * 4] = make_uint4(f2tf(w.x), f2tf(w.y), f2tf(w.z), f2tf(w.w));
    }
    // one edge index per thread (EPT == blockDim.x)
    src_s[tid] = src[e0 + tid];
    dst_s[tid] = dst[e0 + tid];
    if (tid < 128) att_s[tid] = att[tid];

    const int warp = tid >> 5, lane = tid & 31;
    const int wm = warp & 3, wn = warp >> 2;
    const int grp = lane >> 2, tg = lane & 3;

    for (int t = 0; t < EPT / 128; t++) {
        const int e0t = e0 + t * 128;

        float acc[2][8][4];
#pragma unroll
        for (int a = 0; a < 2; a++)
#pragma unroll
            for (int b = 0; b < 8; b++)
#pragma unroll
                for (int k = 0; k < 4; k++) acc[a][b][k] = 0.f;

        // stage chunk 0
        float4 Ar[4];
#pragma unroll
        for (int i = 0; i < 4; i++) {
            int slot = tid + i * 256;
            int r = slot >> 3, c4 = slot & 7;
            Ar[i] = *(const float4*)(EF + (size_t)(e0t + r) * 128 + c4 * 4);
        }
#pragma unroll
        for (int i = 0; i < 4; i++) {
            int slot = tid + i * 256;
            int r = slot >> 3, c4 = slot & 7;
            *(uint4*)&As[0][r][c4 * 4] =
                make_uint4(f2tf(Ar[i].x), f2tf(Ar[i].y), f2tf(Ar[i].z), f2tf(Ar[i].w));
        }

#pragma unroll
        for (int c = 0; c < 4; c++) {
            __syncthreads();
            if (c < 3) {   // prefetch next chunk into regs
                const int kk = (c + 1) * 32;
#pragma unroll
                for (int i = 0; i < 4; i++) {
                    int slot = tid + i * 256;
                    int r = slot >> 3, c4 = slot & 7;
                    Ar[i] = *(const float4*)(EF + (size_t)(e0t + r) * 128 + kk + c4 * 4);
                }
            }
            const int buf = c & 1;
#pragma unroll
            for (int ks = 0; ks < 4; ks++) {
                const int kb = ks * 8;
                const int kw = c * 32 + kb;
                uint32_t af[2][4];
#pragma unroll
                for (int mt = 0; mt < 2; mt++) {
                    int r0 = wm * 32 + mt * 16 + grp;
                    af[mt][0] = As[buf][r0][kb + tg];     af[mt][1] = As[buf][r0 + 8][kb + tg];
                    af[mt][2] = As[buf][r0][kb + tg + 4]; af[mt][3] = As[buf][r0 + 8][kb + tg + 4];
                }
#pragma unroll
                for (int nt = 0; nt < 8; nt++) {
                    int cc = wn * 64 + nt * 8 + grp;
                    uint32_t bf[2];
                    bf[0] = Ws[kw + tg][cc];
                    bf[1] = Ws[kw + tg + 4][cc];
#pragma unroll
                    for (int mt = 0; mt < 2; mt++) mma8(acc[mt][nt], af[mt], bf);
                }
            }
            if (c < 3) {
#pragma unroll
                for (int i = 0; i < 4; i++) {
                    int slot = tid + i * 256;
                    int r = slot >> 3, c4 = slot & 7;
                    *(uint4*)&As[buf ^ 1][r][c4 * 4] =
                        make_uint4(f2tf(Ar[i].x), f2tf(Ar[i].y), f2tf(Ar[i].z), f2tf(Ar[i].w));
                }
            }
        }

        // epilogue: gather x_l[src], x_r[dst], leaky-relu, att-dot, quad reduce
#pragma unroll
        for (int mt = 0; mt < 2; mt++) {
#pragma unroll
            for (int half = 0; half < 2; half++) {
                int row = wm * 32 + mt * 16 + half * 8 + grp;
                const float* xl = g_xl + (size_t)src_s[t * 128 + row] * 128;
                const float* xr = g_xr + (size_t)dst_s[t * 128 + row] * 128;
#pragma unroll
                for (int hh = 0; hh < 2; hh++) {
                    float partial = 0.f;
#pragma unroll
                    for (int ntl = 0; ntl < 4; ntl++) {
                        int nt = hh * 4 + ntl;
                        int col = wn * 64 + nt * 8 + tg * 2;
                        float2 a = *(const float2*)(xl + col);
                        float2 b = *(const float2*)(xr + col);
                        float z0 = acc[mt][nt][half * 2 + 0] + a.x + b.x;
                        float z1 = acc[mt][nt][half * 2 + 1] + a.y + b.y;
                        z0 = (z0 > 0.f) ? z0 : 0.2f * z0;
                        z1 = (z1 > 0.f) ? z1 : 0.2f * z1;
                        partial += z0 * att_s[col] + z1 * att_s[col + 1];
                    }
                    partial += __shfl_xor_sync(0xFFFFFFFFu, partial, 1);
                    partial += __shfl_xor_sync(0xFFFFFFFFu, partial, 2);
                    if (tg == 0)
                        g_logits[(size_t)(e0t + row) * 4 + wn * 2 + hh] = partial;
                }
            }
        }
        if (t == 0) __syncthreads();   // As reuse guard before next tile staging
    }
}

// ---------------- CSR build ----------------
__global__ void zero_cnt_kernel() {
    int i = blockIdx.x * blockDim.x + threadIdx.x;
    if (i < NLR) g_cnt[i] = 0;
}

__global__ void count_kernel(const int* __restrict__ dst) {
    int e = blockIdx.x * blockDim.x + threadIdx.x;
    if (e < ENUM) atomicAdd(&g_cnt[dst[e]], 1);
}

__global__ __launch_bounds__(1024) void scan_kernel() {
    __shared__ int part[1024];
    const int t = threadIdx.x;
    const int CH = (NLR + 1023) / 1024;
    int start = t * CH, end = min(start + CH, NLR);
    int s = 0;
    for (int i = start; i < end; i++) s += g_cnt[i];
    part[t] = s;
    __syncthreads();
    for (int off = 1; off < 1024; off <<= 1) {
        int v = (t >= off) ? part[t - off] : 0;
        __syncthreads();
        part[t] += v;
        __syncthreads();
    }
    int run = part[t] - s;
    for (int i = start; i < end; i++) {
        g_off[i] = run; g_cur[i] = run;
        run += g_cnt[i];
    }
    if (t == 1023) g_off[NLR] = part[1023];
}

__global__ void fill_kernel(const int* __restrict__ dst) {
    int e = blockIdx.x * blockDim.x + threadIdx.x;
    if (e < ENUM) {
        int p = atomicAdd(&g_cur[dst[e]], 1);
        g_elist[p] = e;
    }
}

// =================================================================
// Fused segment softmax + message + b_conv + LayerNorm. 1 block / dst node.
// Alphas computed once per (edge,head) into shared tiles (no redundant exp).
// =================================================================
__global__ __launch_bounds__(128) void message_ln_kernel(
    const int* __restrict__ src,
    const float* __restrict__ bconv,
    const float* __restrict__ lng, const float* __restrict__ lnb)
{
    const int node = blockIdx.x;
    const int tid = threadIdx.x;
    const int w = tid >> 5, lane = tid & 31;
    const int off0 = g_off[node];
    const int deg  = g_off[node + 1] - off0;

    __shared__ float inv_s[4], sv[4], sv2[4];
    __shared__ float alpha_s[4][32];
    __shared__ int   srcs_s[32];

    // online softmax stats, head w per warp
    float m = -1e30f, s = 0.f;
    for (int i = lane; i < deg; i += 32) {
        int e = g_elist[off0 + i];
        float lg = g_logits[(size_t)e * 4 + w];
        if (lg > m) { s *= __expf(m - lg); m = lg; }
        s += __expf(lg - m);
    }
#pragma unroll
    for (int o = 16; o; o >>= 1) {
        float om = __shfl_xor_sync(0xFFFFFFFFu, m, o);
        float os = __shfl_xor_sync(0xFFFFFFFFu, s, o);
        float nm = fmaxf(m, om);
        s = s * __expf(m - nm) + os * __expf(om - nm);
        m = nm;
    }
    if (lane == 0) inv_s[w] = 1.f / (s + 1e-16f);
    __syncthreads();

    // alpha-weighted gather of x_l rows, 32-edge tiles
    const int c = tid;
    float acc = 0.f;
    for (int base = 0; base < deg; base += 32) {
        int n = min(32, deg - base);
        if (lane < n) {
            int e = g_elist[off0 + base + lane];
            if (w == 0) srcs_s[lane] = src[e];
            alpha_s[w][lane] = __expf(g_logits[(size_t)e * 4 + w] - m);
        }
        __syncthreads();
        for (int j = 0; j < n; j++)
            acc = fmaf(alpha_s[w][j], g_xl[(size_t)srcs_s[j] * 128 + c], acc);
        __syncthreads();
    }
    acc *= inv_s[w];           // softmax denominator factored out of the loop

    float msg = acc + bconv[c];

    // LayerNorm over 128 channels
    float v = msg, v2 = msg * msg;
#pragma unroll
    for (int o = 16; o; o >>= 1) {
        v  += __shfl_xor_sync(0xFFFFFFFFu, v,  o);
        v2 += __shfl_xor_sync(0xFFFFFFFFu, v2, o);
    }
    if (lane == 0) { sv[w] = v; sv2[w] = v2; }
    __syncthreads();
    float S  = sv[0] + sv[1] + sv[2] + sv[3];
    float S2 = sv2[0] + sv2[1] + sv2[2] + sv2[3];
    float mu  = S * (1.f / 128.f);
    float var = fmaxf(S2 * (1.f / 128.f) - mu * mu, 0.f);
    float r = rsqrtf(var + 1e-5f);
    g_ln[(size_t)node * 128 + c] = (msg - mu) * r * lng[c] + lnb[c];
}

// =================================================================
extern "C" void kernel_launch(void* const* d_in, const int* in_sizes, int n_in,
                              void* d_out, int out_size) {
    const float* left  = (const float*)d_in[0];
    const int*   eidx  = (const int*)d_in[1];
    const float* ef    = (const float*)d_in[2];
    const float* right = (const float*)d_in[3];
    const float* W_l   = (const float*)d_in[4];
    const float* b_l   = (const float*)d_in[5];
    const float* W_r   = (const float*)d_in[6];
    const float* b_r   = (const float*)d_in[7];
    const float* W_e   = (const float*)d_in[8];
    const float* att   = (const float*)d_in[9];
    const float* bconv = (const float*)d_in[10];
    const float* ln_g  = (const float*)d_in[11];
    const float* ln_b  = (const float*)d_in[12];
    const float* W1    = (const float*)d_in[13];
    const float* b1    = (const float*)d_in[14];
    const float* W2    = (const float*)d_in[15];
    const float* b2    = (const float*)d_in[16];
    float* out = (float*)d_out;

    const int* src = eidx;
    const int* dst = eidx + ENUM;

    float* xl; cudaGetSymbolAddress((void**)&xl, g_xl);
    float* xr; cudaGetSymbolAddress((void**)&xr, g_xr);
    float* ln; cudaGetSymbolAddress((void**)&ln, g_ln);
    float* h1; cudaGetSymbolAddress((void**)&h1, g_h1);

    cudaFuncSetAttribute(edge_logits_kernel,
                         cudaFuncAttributeMaxDynamicSharedMemorySize, SMEM_EDGE);

    const int gblk = (NLR + 127) / 128;   // 391

    // CSR build (independent of GEMMs) first, so launch #6 = edge kernel for ncu
    zero_cnt_kernel<<<(NLR + 255) / 256, 256>>>();
    count_kernel<<<(ENUM + 255) / 256, 256>>>(dst);
    scan_kernel<<<1, 1024>>>();

    // node projections
    gemm128<<<gblk, 256>>>(left,  W_l, 128, nullptr, nullptr, 0, b_l, xl, NLR, 0);
    gemm128<<<gblk, 256>>>(right, W_r, 128, nullptr, nullptr, 0, b_r, xr, NLR, 0);

    // edge logits (fused GEMM + gather + leakyrelu + att dot)  [launch #6]
    edge_logits_kernel<<<ENUM / EPT, 256, SMEM_EDGE>>>(ef, W_e, src, dst, att);

    fill_kernel<<<(ENUM + 255) / 256, 256>>>(dst);

    // segment softmax + message + LN
    message_ln_kernel<<<NLR, 128>>>(src, bconv, ln_g, ln_b);

    // out MLP: h1 = relu([ln, right] @ W1 + b1); out = h1 @ W2 + b2
    gemm128<<<gblk, 256>>>(ln, W1, 128, right, W1 + 128 * 128, 128, b1, h1, NLR, 1);
    gemm128<<<gblk, 256>>>(h1, W2, 128, nullptr, nullptr, 0, b2, out, NLR, 0);
}

// round 5
// speedup vs baseline: 1.4654x; 1.4654x over previous
#include <cuda_runtime.h>
#include <math.h>
#include <stdint.h>

#define NLR  50000
#define EMBD 128
#define ENUM 800000

// ---------------- device scratch (no allocations allowed) ----------------
__device__ float g_logits[(size_t)ENUM * 4];
__device__ float g_xl[(size_t)NLR * EMBD];
__device__ float g_xr[(size_t)NLR * EMBD];
__device__ float g_ln[(size_t)NLR * EMBD];
__device__ float g_h1[(size_t)NLR * EMBD];
__device__ int   g_cnt[NLR];
__device__ int   g_off[NLR + 1];
__device__ int   g_cur[NLR];
__device__ int   g_elist[ENUM];

// ---------------- helpers ----------------
__device__ __forceinline__ uint32_t f2tf(float f) {
    uint32_t u;
    asm("cvt.rna.tf32.f32 %0, %1;" : "=r"(u) : "f"(f));
    return u;
}

__device__ __forceinline__ void mma8(float c[4], const uint32_t a[4], const uint32_t b[2]) {
    asm volatile(
        "mma.sync.aligned.m16n8k8.row.col.f32.tf32.tf32.f32 "
        "{%0,%1,%2,%3},{%4,%5,%6,%7},{%8,%9},{%0,%1,%2,%3};\n"
        : "+f"(c[0]), "+f"(c[1]), "+f"(c[2]), "+f"(c[3])
        : "r"(a[0]), "r"(a[1]), "r"(a[2]), "r"(a[3]), "r"(b[0]), "r"(b[1]));
}

__device__ __forceinline__ void cp16(uint32_t saddr, const float* gptr, int sz) {
    asm volatile("cp.async.cg.shared.global [%0], [%1], 16, %2;\n"
                 :: "r"(saddr), "l"(gptr), "r"(sz));
}
__device__ __forceinline__ void cp_commit() {
    asm volatile("cp.async.commit_group;\n");
}
__device__ __forceinline__ void cp_wait1() {
    asm volatile("cp.async.wait_group 1;\n");
}
__device__ __forceinline__ void cp_wait0() {
    asm volatile("cp.async.wait_group 0;\n");
}

// smem layout sizes (floats, raw fp32 staged by cp.async)
#define AS_BYTES (2 * 128 * 36 * 4)   // 36864
#define BS_BYTES (2 * 32 * 136 * 4)   // 34816
#define SMEM_GEMM (AS_BYTES + BS_BYTES + 512)
#define SMEM_EDGE (AS_BYTES + BS_BYTES + 128 * 4 * 2 + 512)

// =================================================================
// GEMM body: C[M,128] = act( A1[M,K1]@B1 + A2[M,K2]@B2 + bias )
// 2-stage cp.async pipeline, raw fp32 smem, tf32 cvt on consume.
// =================================================================
__device__ __forceinline__ void gemm_body(
    const float* __restrict__ A1, const float* __restrict__ B1, int K1,
    const float* __restrict__ A2, const float* __restrict__ B2, int K2,
    const float* __restrict__ bias, float* __restrict__ C, int M, int doRelu,
    int m0, char* smem_raw)
{
    float (*As)[128][36] = (float(*)[128][36])smem_raw;
    float (*Bs)[32][136] = (float(*)[32][136])(smem_raw + AS_BYTES);
    float* bias_s        = (float*)(smem_raw + AS_BYTES + BS_BYTES);

    const int tid = threadIdx.x;
    if (tid < 128) bias_s[tid] = bias[tid];

    const int warp = tid >> 5, lane = tid & 31;
    const int wm = warp & 3, wn = warp >> 2;
    const int grp = lane >> 2, tg = lane & 3;

    const int nch1 = K1 >> 5;
    const int nch  = nch1 + (K2 >> 5);

    // per-thread staging coords
    const int ra = tid >> 3, ca = (tid & 7) * 4;   // A: 128 rows x 32 cols, 1 x 16B each... (x4 via loop)
    const int rb = tid >> 5, cb = (tid & 31) * 4;  // B: 32 rows x 128 cols

    // stage a chunk into buffer buf
    auto stage = [&](int c, int buf) {
        const float *A, *B; int K, kk;
        if (c < nch1) { A = A1; B = B1; K = K1; kk = c * 32; }
        else          { A = A2; B = B2; K = K2; kk = (c - nch1) * 32; }
#pragma unroll
        for (int i = 0; i < 4; i++) {
            int slot = tid + i * 256;
            int r = slot >> 3, c4 = (slot & 7) * 4;
            int grow = m0 + r;
            int ok = (grow < M);
            const float* gp = A + (size_t)(ok ? grow : 0) * K + kk + c4;
            uint32_t sa = (uint32_t)__cvta_generic_to_shared(&As[buf][r][c4]);
            cp16(sa, gp, ok ? 16 : 0);
        }
#pragma unroll
        for (int i = 0; i < 4; i++) {
            int slot = tid + i * 256;
            int r = slot >> 5, c4 = (slot & 31) * 4;
            const float* gp = B + (size_t)(kk + r) * 128 + c4;
            uint32_t sa = (uint32_t)__cvta_generic_to_shared(&Bs[buf][r][c4]);
            cp16(sa, gp, 16);
        }
        cp_commit();
    };
    (void)ra; (void)ca; (void)rb; (void)cb;

    float acc[2][8][4];
#pragma unroll
    for (int a = 0; a < 2; a++)
#pragma unroll
        for (int b = 0; b < 8; b++)
#pragma unroll
            for (int k = 0; k < 4; k++) acc[a][b][k] = 0.f;

    stage(0, 0);

    for (int c = 0; c < nch; c++) {
        const int buf = c & 1;
        if (c + 1 < nch) { stage(c + 1, buf ^ 1); cp_wait1(); }
        else             { cp_wait0(); }
        __syncthreads();

#pragma unroll
        for (int ks = 0; ks < 4; ks++) {
            const int kb = ks * 8;
            uint32_t af[2][4];
#pragma unroll
            for (int mt = 0; mt < 2; mt++) {
                int r0 = wm * 32 + mt * 16 + grp;
                af[mt][0] = f2tf(As[buf][r0][kb + tg]);
                af[mt][1] = f2tf(As[buf][r0 + 8][kb + tg]);
                af[mt][2] = f2tf(As[buf][r0][kb + tg + 4]);
                af[mt][3] = f2tf(As[buf][r0 + 8][kb + tg + 4]);
            }
#pragma unroll
            for (int nt = 0; nt < 8; nt++) {
                int cc = wn * 64 + nt * 8 + grp;
                uint32_t bf[2];
                bf[0] = f2tf(Bs[buf][kb + tg][cc]);
                bf[1] = f2tf(Bs[buf][kb + tg + 4][cc]);
#pragma unroll
                for (int mt = 0; mt < 2; mt++) mma8(acc[mt][nt], af[mt], bf);
            }
        }
        __syncthreads();
    }

#pragma unroll
    for (int mt = 0; mt < 2; mt++) {
#pragma unroll
        for (int half = 0; half < 2; half++) {
            int grow = m0 + wm * 32 + mt * 16 + half * 8 + grp;
            if (grow < M) {
#pragma unroll
                for (int nt = 0; nt < 8; nt++) {
                    int cc = wn * 64 + nt * 8 + tg * 2;
                    float v0 = acc[mt][nt][half * 2 + 0] + bias_s[cc];
                    float v1 = acc[mt][nt][half * 2 + 1] + bias_s[cc + 1];
                    if (doRelu) { v0 = fmaxf(v0, 0.f); v1 = fmaxf(v1, 0.f); }
                    float2 o; o.x = v0; o.y = v1;
                    *(float2*)(C + (size_t)grow * 128 + cc) = o;
                }
            }
        }
    }
}

__global__ __launch_bounds__(256, 2) void gemm128(
    const float* __restrict__ A1, const float* __restrict__ B1, int K1,
    const float* __restrict__ A2, const float* __restrict__ B2, int K2,
    const float* __restrict__ bias, float* __restrict__ C, int M, int doRelu)
{
    extern __shared__ char smem_raw[];
    gemm_body(A1, B1, K1, A2, B2, K2, bias, C, M, doRelu, blockIdx.x * 128, smem_raw);
}

// node projections merged: blocks [0,half) -> left, [half,2*half) -> right
__global__ __launch_bounds__(256, 2) void gemm_dual(
    const float* __restrict__ Aa, const float* __restrict__ Ba,
    const float* __restrict__ ba, float* __restrict__ Ca,
    const float* __restrict__ Ab, const float* __restrict__ Bb,
    const float* __restrict__ bb, float* __restrict__ Cb,
    int M, int half)
{
    extern __shared__ char smem_raw[];
    if (blockIdx.x < half)
        gemm_body(Aa, Ba, 128, nullptr, nullptr, 0, ba, Ca, M, 0,
                  blockIdx.x * 128, smem_raw);
    else
        gemm_body(Ab, Bb, 128, nullptr, nullptr, 0, bb, Cb, M, 0,
                  (blockIdx.x - half) * 128, smem_raw);
}

// =================================================================
// Fused edge kernel: eproj = EF @ W_e (tf32 mma, never materialized),
// z = leakyrelu(eproj + x_l[src] + x_r[dst], 0.2),
// logits[e,h] = z_h . att_h  -> g_logits[E][4]
// Same cp.async pipeline; 128 edges per block (E % 128 == 0).
// =================================================================
__global__ __launch_bounds__(256, 2) void edge_logits_kernel(
    const float* __restrict__ EF, const float* __restrict__ We,
    const int* __restrict__ src, const int* __restrict__ dst,
    const float* __restrict__ att)
{
    extern __shared__ char smem_raw[];
    float (*As)[128][36] = (float(*)[128][36])smem_raw;
    float (*Bs)[32][136] = (float(*)[32][136])(smem_raw + AS_BYTES);
    int*   src_s = (int*)(smem_raw + AS_BYTES + BS_BYTES);
    int*   dst_s = src_s + 128;
    float* att_s = (float*)(dst_s + 128);

    const int tid = threadIdx.x;
    const int e0  = blockIdx.x * 128;

    if (tid < 128) {
        src_s[tid] = src[e0 + tid];
        dst_s[tid] = dst[e0 + tid];
        att_s[tid] = att[tid];
    }

    const int warp = tid >> 5, lane = tid & 31;
    const int wm = warp & 3, wn = warp >> 2;
    const int grp = lane >> 2, tg = lane & 3;

    auto stage = [&](int c, int buf) {
        const int kk = c * 32;
#pragma unroll
        for (int i = 0; i < 4; i++) {
            int slot = tid + i * 256;
            int r = slot >> 3, c4 = (slot & 7) * 4;
            const float* gp = EF + (size_t)(e0 + r) * 128 + kk + c4;
            uint32_t sa = (uint32_t)__cvta_generic_to_shared(&As[buf][r][c4]);
            cp16(sa, gp, 16);
        }
#pragma unroll
        for (int i = 0; i < 4; i++) {
            int slot = tid + i * 256;
            int r = slot >> 5, c4 = (slot & 31) * 4;
            const float* gp = We + (size_t)(kk + r) * 128 + c4;
            uint32_t sa = (uint32_t)__cvta_generic_to_shared(&Bs[buf][r][c4]);
            cp16(sa, gp, 16);
        }
        cp_commit();
    };

    float acc[2][8][4];
#pragma unroll
    for (int a = 0; a < 2; a++)
#pragma unroll
        for (int b = 0; b < 8; b++)
#pragma unroll
            for (int k = 0; k < 4; k++) acc[a][b][k] = 0.f;

    stage(0, 0);

#pragma unroll
    for (int c = 0; c < 4; c++) {
        const int buf = c & 1;
        if (c < 3) { stage(c + 1, buf ^ 1); cp_wait1(); }
        else       { cp_wait0(); }
        __syncthreads();

#pragma unroll
        for (int ks = 0; ks < 4; ks++) {
            const int kb = ks * 8;
            uint32_t af[2][4];
#pragma unroll
            for (int mt = 0; mt < 2; mt++) {
                int r0 = wm * 32 + mt * 16 + grp;
                af[mt][0] = f2tf(As[buf][r0][kb + tg]);
                af[mt][1] = f2tf(As[buf][r0 + 8][kb + tg]);
                af[mt][2] = f2tf(As[buf][r0][kb + tg + 4]);
                af[mt][3] = f2tf(As[buf][r0 + 8][kb + tg + 4]);
            }
#pragma unroll
            for (int nt = 0; nt < 8; nt++) {
                int cc = wn * 64 + nt * 8 + grp;
                uint32_t bf[2];
                bf[0] = f2tf(Bs[buf][kb + tg][cc]);
                bf[1] = f2tf(Bs[buf][kb + tg + 4][cc]);
#pragma unroll
                for (int mt = 0; mt < 2; mt++) mma8(acc[mt][nt], af[mt], bf);
            }
        }
        __syncthreads();
    }

    // epilogue: gather x_l[src], x_r[dst], leaky-relu, att-dot, quad reduce
#pragma unroll
    for (int mt = 0; mt < 2; mt++) {
#pragma unroll
        for (int half = 0; half < 2; half++) {
            int row = wm * 32 + mt * 16 + half * 8 + grp;
            const float* xl = g_xl + (size_t)src_s[row] * 128;
            const float* xr = g_xr + (size_t)dst_s[row] * 128;
#pragma unroll
            for (int hh = 0; hh < 2; hh++) {
                float partial = 0.f;
#pragma unroll
                for (int ntl = 0; ntl < 4; ntl++) {
                    int nt = hh * 4 + ntl;
                    int col = wn * 64 + nt * 8 + tg * 2;
                    float2 a = *(const float2*)(xl + col);
                    float2 b = *(const float2*)(xr + col);
                    float z0 = acc[mt][nt][half * 2 + 0] + a.x + b.x;
                    float z1 = acc[mt][nt][half * 2 + 1] + a.y + b.y;
                    z0 = (z0 > 0.f) ? z0 : 0.2f * z0;
                    z1 = (z1 > 0.f) ? z1 : 0.2f * z1;
                    partial += z0 * att_s[col] + z1 * att_s[col + 1];
                }
                partial += __shfl_xor_sync(0xFFFFFFFFu, partial, 1);
                partial += __shfl_xor_sync(0xFFFFFFFFu, partial, 2);
                if (tg == 0)
                    g_logits[(size_t)(e0 + row) * 4 + wn * 2 + hh] = partial;
            }
        }
    }
}

// ---------------- CSR build ----------------
__global__ void zero_cnt_kernel() {
    int i = blockIdx.x * blockDim.x + threadIdx.x;
    if (i < NLR) g_cnt[i] = 0;
}

__global__ void count_kernel(const int* __restrict__ dst) {
    int e = blockIdx.x * blockDim.x + threadIdx.x;
    if (e < ENUM) atomicAdd(&g_cnt[dst[e]], 1);
}

__global__ __launch_bounds__(1024) void scan_kernel() {
    __shared__ int part[1024];
    const int t = threadIdx.x;
    const int CH = (NLR + 1023) / 1024;
    int start = t * CH, end = min(start + CH, NLR);
    int s = 0;
    for (int i = start; i < end; i++) s += g_cnt[i];
    part[t] = s;
    __syncthreads();
    for (int off = 1; off < 1024; off <<= 1) {
        int v = (t >= off) ? part[t - off] : 0;
        __syncthreads();
        part[t] += v;
        __syncthreads();
    }
    int run = part[t] - s;
    for (int i = start; i < end; i++) {
        g_off[i] = run; g_cur[i] = run;
        run += g_cnt[i];
    }
    if (t == 1023) g_off[NLR] = part[1023];
}

__global__ void fill_kernel(const int* __restrict__ dst) {
    int e = blockIdx.x * blockDim.x + threadIdx.x;
    if (e < ENUM) {
        int p = atomicAdd(&g_cur[dst[e]], 1);
        g_elist[p] = e;
    }
}

// =================================================================
// Fused segment softmax + message + b_conv + LayerNorm. 1 block / dst node.
// Alphas computed once per (edge,head) into shared tiles.
// =================================================================
__global__ __launch_bounds__(128) void message_ln_kernel(
    const int* __restrict__ src,
    const float* __restrict__ bconv,
    const float* __restrict__ lng, const float* __restrict__ lnb)
{
    const int node = blockIdx.x;
    const int tid = threadIdx.x;
    const int w = tid >> 5, lane = tid & 31;
    const int off0 = g_off[node];
    const int deg  = g_off[node + 1] - off0;

    __shared__ float inv_s[4], sv[4], sv2[4];
    __shared__ float alpha_s[4][32];
    __shared__ int   srcs_s[32];

    // online softmax stats, head w per warp
    float m = -1e30f, s = 0.f;
    for (int i = lane; i < deg; i += 32) {
        int e = g_elist[off0 + i];
        float lg = g_logits[(size_t)e * 4 + w];
        if (lg > m) { s *= __expf(m - lg); m = lg; }
        s += __expf(lg - m);
    }
#pragma unroll
    for (int o = 16; o; o >>= 1) {
        float om = __shfl_xor_sync(0xFFFFFFFFu, m, o);
        float os = __shfl_xor_sync(0xFFFFFFFFu, s, o);
        float nm = fmaxf(m, om);
        s = s * __expf(m - nm) + os * __expf(om - nm);
        m = nm;
    }
    if (lane == 0) inv_s[w] = 1.f / (s + 1e-16f);
    __syncthreads();

    // alpha-weighted gather of x_l rows, 32-edge tiles
    const int c = tid;
    float acc = 0.f;
    for (int base = 0; base < deg; base += 32) {
        int n = min(32, deg - base);
        if (lane < n) {
            int e = g_elist[off0 + base + lane];
            if (w == 0) srcs_s[lane] = src[e];
            alpha_s[w][lane] = __expf(g_logits[(size_t)e * 4 + w] - m);
        }
        __syncthreads();
        for (int j = 0; j < n; j++)
            acc = fmaf(alpha_s[w][j], g_xl[(size_t)srcs_s[j] * 128 + c], acc);
        __syncthreads();
    }
    acc *= inv_s[w];           // softmax denominator factored out

    float msg = acc + bconv[c];

    // LayerNorm over 128 channels
    float v = msg, v2 = msg * msg;
#pragma unroll
    for (int o = 16; o; o >>= 1) {
        v  += __shfl_xor_sync(0xFFFFFFFFu, v,  o);
        v2 += __shfl_xor_sync(0xFFFFFFFFu, v2, o);
    }
    if (lane == 0) { sv[w] = v; sv2[w] = v2; }
    __syncthreads();
    float S  = sv[0] + sv[1] + sv[2] + sv[3];
    float S2 = sv2[0] + sv2[1] + sv2[2] + sv2[3];
    float mu  = S * (1.f / 128.f);
    float var = fmaxf(S2 * (1.f / 128.f) - mu * mu, 0.f);
    float r = rsqrtf(var + 1e-5f);
    g_ln[(size_t)node * 128 + c] = (msg - mu) * r * lng[c] + lnb[c];
}

// =================================================================
extern "C" void kernel_launch(void* const* d_in, const int* in_sizes, int n_in,
                              void* d_out, int out_size) {
    const float* left  = (const float*)d_in[0];
    const int*   eidx  = (const int*)d_in[1];
    const float* ef    = (const float*)d_in[2];
    const float* right = (const float*)d_in[3];
    const float* W_l   = (const float*)d_in[4];
    const float* b_l   = (const float*)d_in[5];
    const float* W_r   = (const float*)d_in[6];
    const float* b_r   = (const float*)d_in[7];
    const float* W_e   = (const float*)d_in[8];
    const float* att   = (const float*)d_in[9];
    const float* bconv = (const float*)d_in[10];
    const float* ln_g  = (const float*)d_in[11];
    const float* ln_b  = (const float*)d_in[12];
    const float* W1    = (const float*)d_in[13];
    const float* b1    = (const float*)d_in[14];
    const float* W2    = (const float*)d_in[15];
    const float* b2    = (const float*)d_in[16];
    float* out = (float*)d_out;

    const int* src = eidx;
    const int* dst = eidx + ENUM;

    float* xl; cudaGetSymbolAddress((void**)&xl, g_xl);
    float* xr; cudaGetSymbolAddress((void**)&xr, g_xr);
    float* ln; cudaGetSymbolAddress((void**)&ln, g_ln);
    float* h1; cudaGetSymbolAddress((void**)&h1, g_h1);

    cudaFuncSetAttribute(gemm128,
                         cudaFuncAttributeMaxDynamicSharedMemorySize, SMEM_GEMM);
    cudaFuncSetAttribute(gemm_dual,
                         cudaFuncAttributeMaxDynamicSharedMemorySize, SMEM_GEMM);
    cudaFuncSetAttribute(edge_logits_kernel,
                         cudaFuncAttributeMaxDynamicSharedMemorySize, SMEM_EDGE);

    const int gblk = (NLR + 127) / 128;   // 391

    // 1-3: CSR prep (independent of GEMMs)
    zero_cnt_kernel<<<(NLR + 255) / 256, 256>>>();
    count_kernel<<<(ENUM + 255) / 256, 256>>>(dst);
    scan_kernel<<<1, 1024>>>();

    // 4: both node projections in one launch
    gemm_dual<<<2 * gblk, 256, SMEM_GEMM>>>(left, W_l, b_l, xl,
                                            right, W_r, b_r, xr, NLR, gblk);

    // 5: CSR fill (independent of GEMMs)
    fill_kernel<<<(ENUM + 255) / 256, 256>>>(dst);

    // 6: edge logits (fused GEMM + gather + leakyrelu + att dot) [profiled]
    edge_logits_kernel<<<ENUM / 128, 256, SMEM_EDGE>>>(ef, W_e, src, dst, att);

    // 7: segment softmax + message + LN
    message_ln_kernel<<<NLR, 128>>>(src, bconv, ln_g, ln_b);

    // 8-9: out MLP: h1 = relu([ln, right] @ W1 + b1); out = h1 @ W2 + b2
    gemm128<<<gblk, 256, SMEM_GEMM>>>(ln, W1, 128, right, W1 + 128 * 128, 128,
                                      b1, h1, NLR, 1);
    gemm128<<<gblk, 256, SMEM_GEMM>>>(h1, W2, 128, nullptr, nullptr, 0,
                                      b2, out, NLR, 0);
}

// round 6
// speedup vs baseline: 1.5592x; 1.0640x over previous
#include <cuda_runtime.h>
#include <math.h>
#include <stdint.h>

#define NLR  50000
#define EMBD 128
#define ENUM 800000

// ---------------- device scratch (no allocations allowed) ----------------
__device__ float g_logits[(size_t)ENUM * 4];
__device__ float g_xl[(size_t)NLR * EMBD];
__device__ float g_xr[(size_t)NLR * EMBD];
__device__ float g_ln[(size_t)NLR * EMBD];
__device__ float g_h1[(size_t)NLR * EMBD];
__device__ int   g_cnt[NLR];
__device__ int   g_off[NLR + 1];
__device__ int   g_cur[NLR];
__device__ int   g_elist[ENUM];

// ---------------- helpers ----------------
__device__ __forceinline__ uint32_t f2tf(float f) {
    uint32_t u;
    asm("cvt.rna.tf32.f32 %0, %1;" : "=r"(u) : "f"(f));
    return u;
}

__device__ __forceinline__ void mma8(float c[4], const uint32_t a[4], const uint32_t b[2]) {
    asm volatile(
        "mma.sync.aligned.m16n8k8.row.col.f32.tf32.tf32.f32 "
        "{%0,%1,%2,%3},{%4,%5,%6,%7},{%8,%9},{%0,%1,%2,%3};\n"
        : "+f"(c[0]), "+f"(c[1]), "+f"(c[2]), "+f"(c[3])
        : "r"(a[0]), "r"(a[1]), "r"(a[2]), "r"(a[3]), "r"(b[0]), "r"(b[1]));
}

__device__ __forceinline__ void cp16(uint32_t saddr, const float* gptr, int sz) {
    asm volatile("cp.async.cg.shared.global [%0], [%1], 16, %2;\n"
                 :: "r"(saddr), "l"(gptr), "r"(sz));
}
__device__ __forceinline__ void cp_commit() {
    asm volatile("cp.async.commit_group;\n");
}
__device__ __forceinline__ void cp_wait1() {
    asm volatile("cp.async.wait_group 1;\n");
}
__device__ __forceinline__ void cp_wait0() {
    asm volatile("cp.async.wait_group 0;\n");
}

// smem layout sizes (floats, raw fp32 staged by cp.async)
#define AS_BYTES (2 * 128 * 36 * 4)   // 36864
#define BS_BYTES (2 * 32 * 136 * 4)   // 34816
#define SMEM_GEMM (AS_BYTES + BS_BYTES + 512)
#define SMEM_EDGE (AS_BYTES + BS_BYTES + 128 * 4 * 2 + 512)

// =================================================================
// GEMM body: C[M,128] = act( A1[M,K1]@B1 + A2[M,K2]@B2 + bias )
// 2-stage cp.async pipeline, raw fp32 smem, tf32 cvt on consume.
// =================================================================
__device__ __forceinline__ void gemm_body(
    const float* __restrict__ A1, const float* __restrict__ B1, int K1,
    const float* __restrict__ A2, const float* __restrict__ B2, int K2,
    const float* __restrict__ bias, float* __restrict__ C, int M, int doRelu,
    int m0, char* smem_raw)
{
    float (*As)[128][36] = (float(*)[128][36])smem_raw;
    float (*Bs)[32][136] = (float(*)[32][136])(smem_raw + AS_BYTES);
    float* bias_s        = (float*)(smem_raw + AS_BYTES + BS_BYTES);

    const int tid = threadIdx.x;
    if (tid < 128) bias_s[tid] = bias[tid];

    const int warp = tid >> 5, lane = tid & 31;
    const int wm = warp & 3, wn = warp >> 2;
    const int grp = lane >> 2, tg = lane & 3;

    const int nch1 = K1 >> 5;
    const int nch  = nch1 + (K2 >> 5);

    auto stage = [&](int c, int buf) {
        const float *A, *B; int K, kk;
        if (c < nch1) { A = A1; B = B1; K = K1; kk = c * 32; }
        else          { A = A2; B = B2; K = K2; kk = (c - nch1) * 32; }
#pragma unroll
        for (int i = 0; i < 4; i++) {
            int slot = tid + i * 256;
            int r = slot >> 3, c4 = (slot & 7) * 4;
            int grow = m0 + r;
            int ok = (grow < M);
            const float* gp = A + (size_t)(ok ? grow : 0) * K + kk + c4;
            uint32_t sa = (uint32_t)__cvta_generic_to_shared(&As[buf][r][c4]);
            cp16(sa, gp, ok ? 16 : 0);
        }
#pragma unroll
        for (int i = 0; i < 4; i++) {
            int slot = tid + i * 256;
            int r = slot >> 5, c4 = (slot & 31) * 4;
            const float* gp = B + (size_t)(kk + r) * 128 + c4;
            uint32_t sa = (uint32_t)__cvta_generic_to_shared(&Bs[buf][r][c4]);
            cp16(sa, gp, 16);
        }
        cp_commit();
    };

    float acc[2][8][4];
#pragma unroll
    for (int a = 0; a < 2; a++)
#pragma unroll
        for (int b = 0; b < 8; b++)
#pragma unroll
            for (int k = 0; k < 4; k++) acc[a][b][k] = 0.f;

    stage(0, 0);

    for (int c = 0; c < nch; c++) {
        const int buf = c & 1;
        if (c + 1 < nch) { stage(c + 1, buf ^ 1); cp_wait1(); }
        else             { cp_wait0(); }
        __syncthreads();

#pragma unroll
        for (int ks = 0; ks < 4; ks++) {
            const int kb = ks * 8;
            uint32_t af[2][4];
#pragma unroll
            for (int mt = 0; mt < 2; mt++) {
                int r0 = wm * 32 + mt * 16 + grp;
                af[mt][0] = f2tf(As[buf][r0][kb + tg]);
                af[mt][1] = f2tf(As[buf][r0 + 8][kb + tg]);
                af[mt][2] = f2tf(As[buf][r0][kb + tg + 4]);
                af[mt][3] = f2tf(As[buf][r0 + 8][kb + tg + 4]);
            }
#pragma unroll
            for (int nt = 0; nt < 8; nt++) {
                int cc = wn * 64 + nt * 8 + grp;
                uint32_t bf[2];
                bf[0] = f2tf(Bs[buf][kb + tg][cc]);
                bf[1] = f2tf(Bs[buf][kb + tg + 4][cc]);
#pragma unroll
                for (int mt = 0; mt < 2; mt++) mma8(acc[mt][nt], af[mt], bf);
            }
        }
        __syncthreads();
    }

#pragma unroll
    for (int mt = 0; mt < 2; mt++) {
#pragma unroll
        for (int half = 0; half < 2; half++) {
            int grow = m0 + wm * 32 + mt * 16 + half * 8 + grp;
            if (grow < M) {
#pragma unroll
                for (int nt = 0; nt < 8; nt++) {
                    int cc = wn * 64 + nt * 8 + tg * 2;
                    float v0 = acc[mt][nt][half * 2 + 0] + bias_s[cc];
                    float v1 = acc[mt][nt][half * 2 + 1] + bias_s[cc + 1];
                    if (doRelu) { v0 = fmaxf(v0, 0.f); v1 = fmaxf(v1, 0.f); }
                    float2 o; o.x = v0; o.y = v1;
                    *(float2*)(C + (size_t)grow * 128 + cc) = o;
                }
            }
        }
    }
}

__global__ __launch_bounds__(256, 2) void gemm128(
    const float* __restrict__ A1, const float* __restrict__ B1, int K1,
    const float* __restrict__ A2, const float* __restrict__ B2, int K2,
    const float* __restrict__ bias, float* __restrict__ C, int M, int doRelu)
{
    extern __shared__ char smem_raw[];
    gemm_body(A1, B1, K1, A2, B2, K2, bias, C, M, doRelu, blockIdx.x * 128, smem_raw);
}

// node projections merged: blocks [0,half) -> left, [half,2*half) -> right
__global__ __launch_bounds__(256, 2) void gemm_dual(
    const float* __restrict__ Aa, const float* __restrict__ Ba,
    const float* __restrict__ ba, float* __restrict__ Ca,
    const float* __restrict__ Ab, const float* __restrict__ Bb,
    const float* __restrict__ bb, float* __restrict__ Cb,
    int M, int half)
{
    extern __shared__ char smem_raw[];
    if (blockIdx.x < half)
        gemm_body(Aa, Ba, 128, nullptr, nullptr, 0, ba, Ca, M, 0,
                  blockIdx.x * 128, smem_raw);
    else
        gemm_body(Ab, Bb, 128, nullptr, nullptr, 0, bb, Cb, M, 0,
                  (blockIdx.x - half) * 128, smem_raw);
}

// =================================================================
// Fused edge kernel: eproj = EF @ W_e (tf32 mma, never materialized),
// z = leakyrelu(eproj + x_l[src] + x_r[dst], 0.2),
// logits[e,h] = z_h . att_h  -> g_logits[E][4]
// =================================================================
__global__ __launch_bounds__(256, 2) void edge_logits_kernel(
    const float* __restrict__ EF, const float* __restrict__ We,
    const int* __restrict__ src, const int* __restrict__ dst,
    const float* __restrict__ att)
{
    extern __shared__ char smem_raw[];
    float (*As)[128][36] = (float(*)[128][36])smem_raw;
    float (*Bs)[32][136] = (float(*)[32][136])(smem_raw + AS_BYTES);
    int*   src_s = (int*)(smem_raw + AS_BYTES + BS_BYTES);
    int*   dst_s = src_s + 128;
    float* att_s = (float*)(dst_s + 128);

    const int tid = threadIdx.x;
    const int e0  = blockIdx.x * 128;

    if (tid < 128) {
        src_s[tid] = src[e0 + tid];
        dst_s[tid] = dst[e0 + tid];
        att_s[tid] = att[tid];
    }

    const int warp = tid >> 5, lane = tid & 31;
    const int wm = warp & 3, wn = warp >> 2;
    const int grp = lane >> 2, tg = lane & 3;

    auto stage = [&](int c, int buf) {
        const int kk = c * 32;
#pragma unroll
        for (int i = 0; i < 4; i++) {
            int slot = tid + i * 256;
            int r = slot >> 3, c4 = (slot & 7) * 4;
            const float* gp = EF + (size_t)(e0 + r) * 128 + kk + c4;
            uint32_t sa = (uint32_t)__cvta_generic_to_shared(&As[buf][r][c4]);
            cp16(sa, gp, 16);
        }
#pragma unroll
        for (int i = 0; i < 4; i++) {
            int slot = tid + i * 256;
            int r = slot >> 5, c4 = (slot & 31) * 4;
            const float* gp = We + (size_t)(kk + r) * 128 + c4;
            uint32_t sa = (uint32_t)__cvta_generic_to_shared(&Bs[buf][r][c4]);
            cp16(sa, gp, 16);
        }
        cp_commit();
    };

    float acc[2][8][4];
#pragma unroll
    for (int a = 0; a < 2; a++)
#pragma unroll
        for (int b = 0; b < 8; b++)
#pragma unroll
            for (int k = 0; k < 4; k++) acc[a][b][k] = 0.f;

    stage(0, 0);

#pragma unroll
    for (int c = 0; c < 4; c++) {
        const int buf = c & 1;
        if (c < 3) { stage(c + 1, buf ^ 1); cp_wait1(); }
        else       { cp_wait0(); }
        __syncthreads();

#pragma unroll
        for (int ks = 0; ks < 4; ks++) {
            const int kb = ks * 8;
            uint32_t af[2][4];
#pragma unroll
            for (int mt = 0; mt < 2; mt++) {
                int r0 = wm * 32 + mt * 16 + grp;
                af[mt][0] = f2tf(As[buf][r0][kb + tg]);
                af[mt][1] = f2tf(As[buf][r0 + 8][kb + tg]);
                af[mt][2] = f2tf(As[buf][r0][kb + tg + 4]);
                af[mt][3] = f2tf(As[buf][r0 + 8][kb + tg + 4]);
            }
#pragma unroll
            for (int nt = 0; nt < 8; nt++) {
                int cc = wn * 64 + nt * 8 + grp;
                uint32_t bf[2];
                bf[0] = f2tf(Bs[buf][kb + tg][cc]);
                bf[1] = f2tf(Bs[buf][kb + tg + 4][cc]);
#pragma unroll
                for (int mt = 0; mt < 2; mt++) mma8(acc[mt][nt], af[mt], bf);
            }
        }
        __syncthreads();
    }

    // epilogue: gather x_l[src], x_r[dst], leaky-relu, att-dot, quad reduce
#pragma unroll
    for (int mt = 0; mt < 2; mt++) {
#pragma unroll
        for (int half = 0; half < 2; half++) {
            int row = wm * 32 + mt * 16 + half * 8 + grp;
            const float* xl = g_xl + (size_t)src_s[row] * 128;
            const float* xr = g_xr + (size_t)dst_s[row] * 128;
#pragma unroll
            for (int hh = 0; hh < 2; hh++) {
                float partial = 0.f;
#pragma unroll
                for (int ntl = 0; ntl < 4; ntl++) {
                    int nt = hh * 4 + ntl;
                    int col = wn * 64 + nt * 8 + tg * 2;
                    float2 a = *(const float2*)(xl + col);
                    float2 b = *(const float2*)(xr + col);
                    float z0 = acc[mt][nt][half * 2 + 0] + a.x + b.x;
                    float z1 = acc[mt][nt][half * 2 + 1] + a.y + b.y;
                    z0 = (z0 > 0.f) ? z0 : 0.2f * z0;
                    z1 = (z1 > 0.f) ? z1 : 0.2f * z1;
                    partial += z0 * att_s[col] + z1 * att_s[col + 1];
                }
                partial += __shfl_xor_sync(0xFFFFFFFFu, partial, 1);
                partial += __shfl_xor_sync(0xFFFFFFFFu, partial, 2);
                if (tg == 0)
                    g_logits[(size_t)(e0 + row) * 4 + wn * 2 + hh] = partial;
            }
        }
    }
}

// ---------------- CSR build ----------------
__global__ void zero_cnt_kernel() {
    int i = blockIdx.x * blockDim.x + threadIdx.x;
    if (i < NLR) g_cnt[i] = 0;
}

__global__ void count_kernel(const int* __restrict__ dst) {
    int e = blockIdx.x * blockDim.x + threadIdx.x;
    if (e < ENUM) atomicAdd(&g_cnt[dst[e]], 1);
}

__global__ __launch_bounds__(1024) void scan_kernel() {
    __shared__ int part[1024];
    const int t = threadIdx.x;
    const int CH = (NLR + 1023) / 1024;
    int start = t * CH, end = min(start + CH, NLR);
    int s = 0;
    for (int i = start; i < end; i++) s += g_cnt[i];
    part[t] = s;
    __syncthreads();
    for (int off = 1; off < 1024; off <<= 1) {
        int v = (t >= off) ? part[t - off] : 0;
        __syncthreads();
        part[t] += v;
        __syncthreads();
    }
    int run = part[t] - s;
    for (int i = start; i < end; i++) {
        g_off[i] = run; g_cur[i] = run;
        run += g_cnt[i];
    }
    if (t == 1023) g_off[NLR] = part[1023];
}

__global__ void fill_kernel(const int* __restrict__ dst) {
    int e = blockIdx.x * blockDim.x + threadIdx.x;
    if (e < ENUM) {
        int p = atomicAdd(&g_cur[dst[e]], 1);
        g_elist[p] = e;
    }
}

// =================================================================
// Warp-per-node fused segment softmax + message + b_conv + LayerNorm.
// Lane l owns channels [4l, 4l+4), head = l>>3. No smem, no barriers.
// =================================================================
__global__ __launch_bounds__(256) void message_ln_kernel(
    const int* __restrict__ src,
    const float* __restrict__ bconv,
    const float* __restrict__ lng, const float* __restrict__ lnb)
{
    const int node = (blockIdx.x * blockDim.x + threadIdx.x) >> 5;
    const int lane = threadIdx.x & 31;
    if (node >= NLR) return;

    const int h  = lane >> 3;
    const int c4 = lane * 4;
    const int off0 = g_off[node];
    const int deg  = g_off[node + 1] - off0;

    // pass 1: per-head max (float4 over heads)
    float4 mx = make_float4(-1e30f, -1e30f, -1e30f, -1e30f);
    for (int i = lane; i < deg; i += 32) {
        int e = __ldg(&g_elist[off0 + i]);
        float4 lg = *(const float4*)&g_logits[(size_t)e * 4];
        mx.x = fmaxf(mx.x, lg.x); mx.y = fmaxf(mx.y, lg.y);
        mx.z = fmaxf(mx.z, lg.z); mx.w = fmaxf(mx.w, lg.w);
    }
#pragma unroll
    for (int o = 16; o; o >>= 1) {
        mx.x = fmaxf(mx.x, __shfl_xor_sync(0xFFFFFFFFu, mx.x, o));
        mx.y = fmaxf(mx.y, __shfl_xor_sync(0xFFFFFFFFu, mx.y, o));
        mx.z = fmaxf(mx.z, __shfl_xor_sync(0xFFFFFFFFu, mx.z, o));
        mx.w = fmaxf(mx.w, __shfl_xor_sync(0xFFFFFFFFu, mx.w, o));
    }

    // pass 2: per-head sum of exp
    float4 sm = make_float4(0.f, 0.f, 0.f, 0.f);
    for (int i = lane; i < deg; i += 32) {
        int e = __ldg(&g_elist[off0 + i]);
        float4 lg = *(const float4*)&g_logits[(size_t)e * 4];
        sm.x += __expf(lg.x - mx.x); sm.y += __expf(lg.y - mx.y);
        sm.z += __expf(lg.z - mx.z); sm.w += __expf(lg.w - mx.w);
    }
#pragma unroll
    for (int o = 16; o; o >>= 1) {
        sm.x += __shfl_xor_sync(0xFFFFFFFFu, sm.x, o);
        sm.y += __shfl_xor_sync(0xFFFFFFFFu, sm.y, o);
        sm.z += __shfl_xor_sync(0xFFFFFFFFu, sm.z, o);
        sm.w += __shfl_xor_sync(0xFFFFFFFFu, sm.w, o);
    }

    const float m_h = (h == 0) ? mx.x : (h == 1) ? mx.y : (h == 2) ? mx.z : mx.w;
    const float s_h = (h == 0) ? sm.x : (h == 1) ? sm.y : (h == 2) ? sm.z : sm.w;
    const float inv_h = 1.f / (s_h + 1e-16f);

    // main: alpha-weighted gather of x_l rows (1 float4 per lane per edge)
    float4 acc = make_float4(0.f, 0.f, 0.f, 0.f);
    for (int j = 0; j < deg; j++) {
        int e  = __ldg(&g_elist[off0 + j]);
        int sr = __ldg(&src[e]);
        float a = __expf(__ldg(&g_logits[(size_t)e * 4 + h]) - m_h);
        float4 x = *(const float4*)&g_xl[(size_t)sr * 128 + c4];
        acc.x = fmaf(a, x.x, acc.x); acc.y = fmaf(a, x.y, acc.y);
        acc.z = fmaf(a, x.z, acc.z); acc.w = fmaf(a, x.w, acc.w);
    }
    float4 bc = *(const float4*)&bconv[c4];
    float4 msg;
    msg.x = acc.x * inv_h + bc.x; msg.y = acc.y * inv_h + bc.y;
    msg.z = acc.z * inv_h + bc.z; msg.w = acc.w * inv_h + bc.w;

    // LayerNorm over 128 channels (warp reduce of sum, sumsq)
    float s1 = msg.x + msg.y + msg.z + msg.w;
    float s2 = msg.x * msg.x + msg.y * msg.y + msg.z * msg.z + msg.w * msg.w;
#pragma unroll
    for (int o = 16; o; o >>= 1) {
        s1 += __shfl_xor_sync(0xFFFFFFFFu, s1, o);
        s2 += __shfl_xor_sync(0xFFFFFFFFu, s2, o);
    }
    float mu  = s1 * (1.f / 128.f);
    float var = fmaxf(s2 * (1.f / 128.f) - mu * mu, 0.f);
    float r = rsqrtf(var + 1e-5f);

    float4 g = *(const float4*)&lng[c4];
    float4 b = *(const float4*)&lnb[c4];
    float4 o4;
    o4.x = (msg.x - mu) * r * g.x + b.x;
    o4.y = (msg.y - mu) * r * g.y + b.y;
    o4.z = (msg.z - mu) * r * g.z + b.z;
    o4.w = (msg.w - mu) * r * g.w + b.w;
    *(float4*)&g_ln[(size_t)node * 128 + c4] = o4;
}

// =================================================================
extern "C" void kernel_launch(void* const* d_in, const int* in_sizes, int n_in,
                              void* d_out, int out_size) {
    const float* left  = (const float*)d_in[0];
    const int*   eidx  = (const int*)d_in[1];
    const float* ef    = (const float*)d_in[2];
    const float* right = (const float*)d_in[3];
    const float* W_l   = (const float*)d_in[4];
    const float* b_l   = (const float*)d_in[5];
    const float* W_r   = (const float*)d_in[6];
    const float* b_r   = (const float*)d_in[7];
    const float* W_e   = (const float*)d_in[8];
    const float* att   = (const float*)d_in[9];
    const float* bconv = (const float*)d_in[10];
    const float* ln_g  = (const float*)d_in[11];
    const float* ln_b  = (const float*)d_in[12];
    const float* W1    = (const float*)d_in[13];
    const float* b1    = (const float*)d_in[14];
    const float* W2    = (const float*)d_in[15];
    const float* b2    = (const float*)d_in[16];
    float* out = (float*)d_out;

    const int* src = eidx;
    const int* dst = eidx + ENUM;

    float* xl; cudaGetSymbolAddress((void**)&xl, g_xl);
    float* xr; cudaGetSymbolAddress((void**)&xr, g_xr);
    float* ln; cudaGetSymbolAddress((void**)&ln, g_ln);
    float* h1; cudaGetSymbolAddress((void**)&h1, g_h1);

    cudaFuncSetAttribute(gemm128,
                         cudaFuncAttributeMaxDynamicSharedMemorySize, SMEM_GEMM);
    cudaFuncSetAttribute(gemm_dual,
                         cudaFuncAttributeMaxDynamicSharedMemorySize, SMEM_GEMM);
    cudaFuncSetAttribute(edge_logits_kernel,
                         cudaFuncAttributeMaxDynamicSharedMemorySize, SMEM_EDGE);

    const int gblk = (NLR + 127) / 128;   // 391

    // 1: counter init (independent)
    zero_cnt_kernel<<<(NLR + 255) / 256, 256>>>();
    // 2: node projections
    gemm_dual<<<2 * gblk, 256, SMEM_GEMM>>>(left, W_l, b_l, xl,
                                            right, W_r, b_r, xr, NLR, gblk);
    // 3: degree count (independent of GEMMs)
    count_kernel<<<(ENUM + 255) / 256, 256>>>(dst);
    // 4: edge logits — profiled slot
    edge_logits_kernel<<<ENUM / 128, 256, SMEM_EDGE>>>(ef, W_e, src, dst, att);
    // 5-6: CSR scan + fill
    scan_kernel<<<1, 1024>>>();
    fill_kernel<<<(ENUM + 255) / 256, 256>>>(dst);
    // 7: warp-per-node segment softmax + message + LN
    message_ln_kernel<<<(NLR * 32 + 255) / 256, 256>>>(src, bconv, ln_g, ln_b);
    // 8-9: out MLP
    gemm128<<<gblk, 256, SMEM_GEMM>>>(ln, W1, 128, right, W1 + 128 * 128, 128,
                                      b1, h1, NLR, 1);
    gemm128<<<gblk, 256, SMEM_GEMM>>>(h1, W2, 128, nullptr, nullptr, 0,
                                      b2, out, NLR, 0);
}

// round 7
// speedup vs baseline: 1.7081x; 1.0955x over previous
#include <cuda_runtime.h>
#include <cuda_fp16.h>
#include <math.h>
#include <stdint.h>

#define NLR  50000
#define EMBD 128
#define ENUM 800000

#define AS_F 40    // padded A row length (floats): banks 8*grp+2*tg all distinct
#define BS_F 132   // padded B row length (floats): banks 8*tg+grp all distinct

// ---------------- device scratch (no allocations allowed) ----------------
__device__ float g_logits[(size_t)ENUM * 4];
__device__ float g_xl[(size_t)NLR * EMBD];
__device__ float g_xr[(size_t)NLR * EMBD];
__device__ float g_ln[(size_t)NLR * EMBD];
__device__ float g_h1[(size_t)NLR * EMBD];
__device__ int   g_cnt[NLR];
__device__ int   g_off[NLR + 1];
__device__ int   g_cur[NLR];
__device__ int   g_elist[ENUM];

// ---------------- helpers ----------------
__device__ __forceinline__ uint32_t f2h2(float lo, float hi) {
    __half2 h = __floats2half2_rn(lo, hi);
    return *(uint32_t*)&h;
}

__device__ __forceinline__ void mma16(float c[4], const uint32_t a[4], const uint32_t b[2]) {
    asm volatile(
        "mma.sync.aligned.m16n8k16.row.col.f32.f16.f16.f32 "
        "{%0,%1,%2,%3},{%4,%5,%6,%7},{%8,%9},{%0,%1,%2,%3};\n"
        : "+f"(c[0]), "+f"(c[1]), "+f"(c[2]), "+f"(c[3])
        : "r"(a[0]), "r"(a[1]), "r"(a[2]), "r"(a[3]), "r"(b[0]), "r"(b[1]));
}

__device__ __forceinline__ void cp16(uint32_t saddr, const float* gptr, int sz) {
    asm volatile("cp.async.cg.shared.global [%0], [%1], 16, %2;\n"
                 :: "r"(saddr), "l"(gptr), "r"(sz));
}
__device__ __forceinline__ void cp_commit() {
    asm volatile("cp.async.commit_group;\n");
}
__device__ __forceinline__ void cp_wait1() {
    asm volatile("cp.async.wait_group 1;\n");
}
__device__ __forceinline__ void cp_wait0() {
    asm volatile("cp.async.wait_group 0;\n");
}

// smem layout sizes (raw fp32 staged by cp.async, fp16 cvt on consume)
#define AS_BYTES (2 * 128 * AS_F * 4)   // 40960
#define BS_BYTES (2 * 32 * BS_F * 4)    // 33792
#define SMEM_GEMM (AS_BYTES + BS_BYTES + 512)
#define SMEM_EDGE (AS_BYTES + BS_BYTES + 128 * 4 * 2 + 512)

// =================================================================
// GEMM body: C[M,128] = act( A1[M,K1]@B1 + A2[M,K2]@B2 + bias )
// 2-stage cp.async pipeline, fp16 m16n8k16 mma, fp32 accum.
// =================================================================
__device__ __forceinline__ void gemm_body(
    const float* __restrict__ A1, const float* __restrict__ B1, int K1,
    const float* __restrict__ A2, const float* __restrict__ B2, int K2,
    const float* __restrict__ bias, float* __restrict__ C, int M, int doRelu,
    int m0, char* smem_raw)
{
    float (*As)[128][AS_F] = (float(*)[128][AS_F])smem_raw;
    float (*Bs)[32][BS_F]  = (float(*)[32][BS_F])(smem_raw + AS_BYTES);
    float* bias_s          = (float*)(smem_raw + AS_BYTES + BS_BYTES);

    const int tid = threadIdx.x;
    if (tid < 128) bias_s[tid] = bias[tid];

    const int warp = tid >> 5, lane = tid & 31;
    const int wm = warp & 3, wn = warp >> 2;
    const int grp = lane >> 2, tg = lane & 3;

    const int nch1 = K1 >> 5;
    const int nch  = nch1 + (K2 >> 5);

    auto stage = [&](int c, int buf) {
        const float *A, *B; int K, kk;
        if (c < nch1) { A = A1; B = B1; K = K1; kk = c * 32; }
        else          { A = A2; B = B2; K = K2; kk = (c - nch1) * 32; }
#pragma unroll
        for (int i = 0; i < 4; i++) {
            int slot = tid + i * 256;
            int r = slot >> 3, c4 = (slot & 7) * 4;
            int grow = m0 + r;
            int ok = (grow < M);
            const float* gp = A + (size_t)(ok ? grow : 0) * K + kk + c4;
            uint32_t sa = (uint32_t)__cvta_generic_to_shared(&As[buf][r][c4]);
            cp16(sa, gp, ok ? 16 : 0);
        }
#pragma unroll
        for (int i = 0; i < 4; i++) {
            int slot = tid + i * 256;
            int r = slot >> 5, c4 = (slot & 31) * 4;
            const float* gp = B + (size_t)(kk + r) * 128 + c4;
            uint32_t sa = (uint32_t)__cvta_generic_to_shared(&Bs[buf][r][c4]);
            cp16(sa, gp, 16);
        }
        cp_commit();
    };

    float acc[2][8][4];
#pragma unroll
    for (int a = 0; a < 2; a++)
#pragma unroll
        for (int b = 0; b < 8; b++)
#pragma unroll
            for (int k = 0; k < 4; k++) acc[a][b][k] = 0.f;

    stage(0, 0);

    for (int c = 0; c < nch; c++) {
        const int buf = c & 1;
        if (c + 1 < nch) { stage(c + 1, buf ^ 1); cp_wait1(); }
        else             { cp_wait0(); }
        __syncthreads();

#pragma unroll
        for (int ks = 0; ks < 2; ks++) {
            const int kb = ks * 16;
            uint32_t af[2][4];
#pragma unroll
            for (int mt = 0; mt < 2; mt++) {
                int r0 = wm * 32 + mt * 16 + grp;
                float2 p0 = *(const float2*)&As[buf][r0][kb + 2 * tg];
                float2 p1 = *(const float2*)&As[buf][r0 + 8][kb + 2 * tg];
                float2 p2 = *(const float2*)&As[buf][r0][kb + 2 * tg + 8];
                float2 p3 = *(const float2*)&As[buf][r0 + 8][kb + 2 * tg + 8];
                af[mt][0] = f2h2(p0.x, p0.y);
                af[mt][1] = f2h2(p1.x, p1.y);
                af[mt][2] = f2h2(p2.x, p2.y);
                af[mt][3] = f2h2(p3.x, p3.y);
            }
#pragma unroll
            for (int nt = 0; nt < 8; nt++) {
                int cc = wn * 64 + nt * 8 + grp;
                uint32_t bf[2];
                bf[0] = f2h2(Bs[buf][kb + 2 * tg][cc],     Bs[buf][kb + 2 * tg + 1][cc]);
                bf[1] = f2h2(Bs[buf][kb + 2 * tg + 8][cc], Bs[buf][kb + 2 * tg + 9][cc]);
#pragma unroll
                for (int mt = 0; mt < 2; mt++) mma16(acc[mt][nt], af[mt], bf);
            }
        }
        __syncthreads();
    }

#pragma unroll
    for (int mt = 0; mt < 2; mt++) {
#pragma unroll
        for (int half = 0; half < 2; half++) {
            int grow = m0 + wm * 32 + mt * 16 + half * 8 + grp;
            if (grow < M) {
#pragma unroll
                for (int nt = 0; nt < 8; nt++) {
                    int cc = wn * 64 + nt * 8 + tg * 2;
                    float v0 = acc[mt][nt][half * 2 + 0] + bias_s[cc];
                    float v1 = acc[mt][nt][half * 2 + 1] + bias_s[cc + 1];
                    if (doRelu) { v0 = fmaxf(v0, 0.f); v1 = fmaxf(v1, 0.f); }
                    float2 o; o.x = v0; o.y = v1;
                    *(float2*)(C + (size_t)grow * 128 + cc) = o;
                }
            }
        }
    }
}

__global__ __launch_bounds__(256, 2) void gemm128(
    const float* __restrict__ A1, const float* __restrict__ B1, int K1,
    const float* __restrict__ A2, const float* __restrict__ B2, int K2,
    const float* __restrict__ bias, float* __restrict__ C, int M, int doRelu)
{
    extern __shared__ char smem_raw[];
    gemm_body(A1, B1, K1, A2, B2, K2, bias, C, M, doRelu, blockIdx.x * 128, smem_raw);
}

// node projections merged: blocks [0,half) -> left, [half,2*half) -> right
__global__ __launch_bounds__(256, 2) void gemm_dual(
    const float* __restrict__ Aa, const float* __restrict__ Ba,
    const float* __restrict__ ba, float* __restrict__ Ca,
    const float* __restrict__ Ab, const float* __restrict__ Bb,
    const float* __restrict__ bb, float* __restrict__ Cb,
    int M, int half)
{
    extern __shared__ char smem_raw[];
    if (blockIdx.x < half)
        gemm_body(Aa, Ba, 128, nullptr, nullptr, 0, ba, Ca, M, 0,
                  blockIdx.x * 128, smem_raw);
    else
        gemm_body(Ab, Bb, 128, nullptr, nullptr, 0, bb, Cb, M, 0,
                  (blockIdx.x - half) * 128, smem_raw);
}

// =================================================================
// Fused edge kernel: eproj = EF @ W_e (fp16 mma, never materialized),
// z = leakyrelu(eproj + x_l[src] + x_r[dst], 0.2),
// logits[e,h] = z_h . att_h  -> g_logits[E][4]
// =================================================================
__global__ __launch_bounds__(256, 2) void edge_logits_kernel(
    const float* __restrict__ EF, const float* __restrict__ We,
    const int* __restrict__ src, const int* __restrict__ dst,
    const float* __restrict__ att)
{
    extern __shared__ char smem_raw[];
    float (*As)[128][AS_F] = (float(*)[128][AS_F])smem_raw;
    float (*Bs)[32][BS_F]  = (float(*)[32][BS_F])(smem_raw + AS_BYTES);
    int*   src_s = (int*)(smem_raw + AS_BYTES + BS_BYTES);
    int*   dst_s = src_s + 128;
    float* att_s = (float*)(dst_s + 128);

    const int tid = threadIdx.x;
    const int e0  = blockIdx.x * 128;

    if (tid < 128) {
        src_s[tid] = src[e0 + tid];
        dst_s[tid] = dst[e0 + tid];
        att_s[tid] = att[tid];
    }

    const int warp = tid >> 5, lane = tid & 31;
    const int wm = warp & 3, wn = warp >> 2;
    const int grp = lane >> 2, tg = lane & 3;

    auto stage = [&](int c, int buf) {
        const int kk = c * 32;
#pragma unroll
        for (int i = 0; i < 4; i++) {
            int slot = tid + i * 256;
            int r = slot >> 3, c4 = (slot & 7) * 4;
            const float* gp = EF + (size_t)(e0 + r) * 128 + kk + c4;
            uint32_t sa = (uint32_t)__cvta_generic_to_shared(&As[buf][r][c4]);
            cp16(sa, gp, 16);
        }
#pragma unroll
        for (int i = 0; i < 4; i++) {
            int slot = tid + i * 256;
            int r = slot >> 5, c4 = (slot & 31) * 4;
            const float* gp = We + (size_t)(kk + r) * 128 + c4;
            uint32_t sa = (uint32_t)__cvta_generic_to_shared(&Bs[buf][r][c4]);
            cp16(sa, gp, 16);
        }
        cp_commit();
    };

    float acc[2][8][4];
#pragma unroll
    for (int a = 0; a < 2; a++)
#pragma unroll
        for (int b = 0; b < 8; b++)
#pragma unroll
            for (int k = 0; k < 4; k++) acc[a][b][k] = 0.f;

    stage(0, 0);

#pragma unroll
    for (int c = 0; c < 4; c++) {
        const int buf = c & 1;
        if (c < 3) { stage(c + 1, buf ^ 1); cp_wait1(); }
        else       { cp_wait0(); }
        __syncthreads();

#pragma unroll
        for (int ks = 0; ks < 2; ks++) {
            const int kb = ks * 16;
            uint32_t af[2][4];
#pragma unroll
            for (int mt = 0; mt < 2; mt++) {
                int r0 = wm * 32 + mt * 16 + grp;
                float2 p0 = *(const float2*)&As[buf][r0][kb + 2 * tg];
                float2 p1 = *(const float2*)&As[buf][r0 + 8][kb + 2 * tg];
                float2 p2 = *(const float2*)&As[buf][r0][kb + 2 * tg + 8];
                float2 p3 = *(const float2*)&As[buf][r0 + 8][kb + 2 * tg + 8];
                af[mt][0] = f2h2(p0.x, p0.y);
                af[mt][1] = f2h2(p1.x, p1.y);
                af[mt][2] = f2h2(p2.x, p2.y);
                af[mt][3] = f2h2(p3.x, p3.y);
            }
#pragma unroll
            for (int nt = 0; nt < 8; nt++) {
                int cc = wn * 64 + nt * 8 + grp;
                uint32_t bf[2];
                bf[0] = f2h2(Bs[buf][kb + 2 * tg][cc],     Bs[buf][kb + 2 * tg + 1][cc]);
                bf[1] = f2h2(Bs[buf][kb + 2 * tg + 8][cc], Bs[buf][kb + 2 * tg + 9][cc]);
#pragma unroll
                for (int mt = 0; mt < 2; mt++) mma16(acc[mt][nt], af[mt], bf);
            }
        }
        __syncthreads();
    }

    // epilogue: gather x_l[src], x_r[dst], leaky-relu, att-dot, quad reduce
#pragma unroll
    for (int mt = 0; mt < 2; mt++) {
#pragma unroll
        for (int half = 0; half < 2; half++) {
            int row = wm * 32 + mt * 16 + half * 8 + grp;
            const float* xl = g_xl + (size_t)src_s[row] * 128;
            const float* xr = g_xr + (size_t)dst_s[row] * 128;
#pragma unroll
            for (int hh = 0; hh < 2; hh++) {
                float partial = 0.f;
#pragma unroll
                for (int ntl = 0; ntl < 4; ntl++) {
                    int nt = hh * 4 + ntl;
                    int col = wn * 64 + nt * 8 + tg * 2;
                    float2 a = *(const float2*)(xl + col);
                    float2 b = *(const float2*)(xr + col);
                    float z0 = acc[mt][nt][half * 2 + 0] + a.x + b.x;
                    float z1 = acc[mt][nt][half * 2 + 1] + a.y + b.y;
                    z0 = (z0 > 0.f) ? z0 : 0.2f * z0;
                    z1 = (z1 > 0.f) ? z1 : 0.2f * z1;
                    partial += z0 * att_s[col] + z1 * att_s[col + 1];
                }
                partial += __shfl_xor_sync(0xFFFFFFFFu, partial, 1);
                partial += __shfl_xor_sync(0xFFFFFFFFu, partial, 2);
                if (tg == 0)
                    g_logits[(size_t)(e0 + row) * 4 + wn * 2 + hh] = partial;
            }
        }
    }
}

// ---------------- CSR build ----------------
__global__ void zero_cnt_kernel() {
    int i = blockIdx.x * blockDim.x + threadIdx.x;
    if (i < NLR) g_cnt[i] = 0;
}

__global__ void count_kernel(const int* __restrict__ dst) {
    int e = blockIdx.x * blockDim.x + threadIdx.x;
    if (e < ENUM) atomicAdd(&g_cnt[dst[e]], 1);
}

__global__ __launch_bounds__(1024) void scan_kernel() {
    __shared__ int part[1024];
    const int t = threadIdx.x;
    const int CH = (NLR + 1023) / 1024;
    int start = t * CH, end = min(start + CH, NLR);
    int s = 0;
    for (int i = start; i < end; i++) s += g_cnt[i];
    part[t] = s;
    __syncthreads();
    for (int off = 1; off < 1024; off <<= 1) {
        int v = (t >= off) ? part[t - off] : 0;
        __syncthreads();
        part[t] += v;
        __syncthreads();
    }
    int run = part[t] - s;
    for (int i = start; i < end; i++) {
        g_off[i] = run; g_cur[i] = run;
        run += g_cnt[i];
    }
    if (t == 1023) g_off[NLR] = part[1023];
}

__global__ void fill_kernel(const int* __restrict__ dst) {
    int e = blockIdx.x * blockDim.x + threadIdx.x;
    if (e < ENUM) {
        int p = atomicAdd(&g_cur[dst[e]], 1);
        g_elist[p] = e;
    }
}

// =================================================================
// Warp-per-node fused segment softmax + message + b_conv + LayerNorm.
// Lane l owns channels [4l, 4l+4), head = l>>3. No smem, no barriers.
// =================================================================
__global__ __launch_bounds__(256) void message_ln_kernel(
    const int* __restrict__ src,
    const float* __restrict__ bconv,
    const float* __restrict__ lng, const float* __restrict__ lnb)
{
    const int node = (blockIdx.x * blockDim.x + threadIdx.x) >> 5;
    const int lane = threadIdx.x & 31;
    if (node >= NLR) return;

    const int h  = lane >> 3;
    const int c4 = lane * 4;
    const int off0 = g_off[node];
    const int deg  = g_off[node + 1] - off0;

    // pass 1: per-head max (float4 over heads)
    float4 mx = make_float4(-1e30f, -1e30f, -1e30f, -1e30f);
    for (int i = lane; i < deg; i += 32) {
        int e = __ldg(&g_elist[off0 + i]);
        float4 lg = *(const float4*)&g_logits[(size_t)e * 4];
        mx.x = fmaxf(mx.x, lg.x); mx.y = fmaxf(mx.y, lg.y);
        mx.z = fmaxf(mx.z, lg.z); mx.w = fmaxf(mx.w, lg.w);
    }
#pragma unroll
    for (int o = 16; o; o >>= 1) {
        mx.x = fmaxf(mx.x, __shfl_xor_sync(0xFFFFFFFFu, mx.x, o));
        mx.y = fmaxf(mx.y, __shfl_xor_sync(0xFFFFFFFFu, mx.y, o));
        mx.z = fmaxf(mx.z, __shfl_xor_sync(0xFFFFFFFFu, mx.z, o));
        mx.w = fmaxf(mx.w, __shfl_xor_sync(0xFFFFFFFFu, mx.w, o));
    }

    // pass 2: per-head sum of exp
    float4 sm = make_float4(0.f, 0.f, 0.f, 0.f);
    for (int i = lane; i < deg; i += 32) {
        int e = __ldg(&g_elist[off0 + i]);
        float4 lg = *(const float4*)&g_logits[(size_t)e * 4];
        sm.x += __expf(lg.x - mx.x); sm.y += __expf(lg.y - mx.y);
        sm.z += __expf(lg.z - mx.z); sm.w += __expf(lg.w - mx.w);
    }
#pragma unroll
    for (int o = 16; o; o >>= 1) {
        sm.x += __shfl_xor_sync(0xFFFFFFFFu, sm.x, o);
        sm.y += __shfl_xor_sync(0xFFFFFFFFu, sm.y, o);
        sm.z += __shfl_xor_sync(0xFFFFFFFFu, sm.z, o);
        sm.w += __shfl_xor_sync(0xFFFFFFFFu, sm.w, o);
    }

    const float m_h = (h == 0) ? mx.x : (h == 1) ? mx.y : (h == 2) ? mx.z : mx.w;
    const float s_h = (h == 0) ? sm.x : (h == 1) ? sm.y : (h == 2) ? sm.z : sm.w;
    const float inv_h = 1.f / (s_h + 1e-16f);

    // main: alpha-weighted gather of x_l rows (1 float4 per lane per edge)
    float4 acc = make_float4(0.f, 0.f, 0.f, 0.f);
    for (int j = 0; j < deg; j++) {
        int e  = __ldg(&g_elist[off0 + j]);
        int sr = __ldg(&src[e]);
        float a = __expf(__ldg(&g_logits[(size_t)e * 4 + h]) - m_h);
        float4 x = *(const float4*)&g_xl[(size_t)sr * 128 + c4];
        acc.x = fmaf(a, x.x, acc.x); acc.y = fmaf(a, x.y, acc.y);
        acc.z = fmaf(a, x.z, acc.z); acc.w = fmaf(a, x.w, acc.w);
    }
    float4 bc = *(const float4*)&bconv[c4];
    float4 msg;
    msg.x = acc.x * inv_h + bc.x; msg.y = acc.y * inv_h + bc.y;
    msg.z = acc.z * inv_h + bc.z; msg.w = acc.w * inv_h + bc.w;

    // LayerNorm over 128 channels (warp reduce of sum, sumsq)
    float s1 = msg.x + msg.y + msg.z + msg.w;
    float s2 = msg.x * msg.x + msg.y * msg.y + msg.z * msg.z + msg.w * msg.w;
#pragma unroll
    for (int o = 16; o; o >>= 1) {
        s1 += __shfl_xor_sync(0xFFFFFFFFu, s1, o);
        s2 += __shfl_xor_sync(0xFFFFFFFFu, s2, o);
    }
    float mu  = s1 * (1.f / 128.f);
    float var = fmaxf(s2 * (1.f / 128.f) - mu * mu, 0.f);
    float r = rsqrtf(var + 1e-5f);

    float4 g = *(const float4*)&lng[c4];
    float4 b = *(const float4*)&lnb[c4];
    float4 o4;
    o4.x = (msg.x - mu) * r * g.x + b.x;
    o4.y = (msg.y - mu) * r * g.y + b.y;
    o4.z = (msg.z - mu) * r * g.z + b.z;
    o4.w = (msg.w - mu) * r * g.w + b.w;
    *(float4*)&g_ln[(size_t)node * 128 + c4] = o4;
}

// =================================================================
extern "C" void kernel_launch(void* const* d_in, const int* in_sizes, int n_in,
                              void* d_out, int out_size) {
    const float* left  = (const float*)d_in[0];
    const int*   eidx  = (const int*)d_in[1];
    const float* ef    = (const float*)d_in[2];
    const float* right = (const float*)d_in[3];
    const float* W_l   = (const float*)d_in[4];
    const float* b_l   = (const float*)d_in[5];
    const float* W_r   = (const float*)d_in[6];
    const float* b_r   = (const float*)d_in[7];
    const float* W_e   = (const float*)d_in[8];
    const float* att   = (const float*)d_in[9];
    const float* bconv = (const float*)d_in[10];
    const float* ln_g  = (const float*)d_in[11];
    const float* ln_b  = (const float*)d_in[12];
    const float* W1    = (const float*)d_in[13];
    const float* b1    = (const float*)d_in[14];
    const float* W2    = (const float*)d_in[15];
    const float* b2    = (const float*)d_in[16];
    float* out = (float*)d_out;

    const int* src = eidx;
    const int* dst = eidx + ENUM;

    float* xl; cudaGetSymbolAddress((void**)&xl, g_xl);
    float* xr; cudaGetSymbolAddress((void**)&xr, g_xr);
    float* ln; cudaGetSymbolAddress((void**)&ln, g_ln);
    float* h1; cudaGetSymbolAddress((void**)&h1, g_h1);

    cudaFuncSetAttribute(gemm128,
                         cudaFuncAttributeMaxDynamicSharedMemorySize, SMEM_GEMM);
    cudaFuncSetAttribute(gemm_dual,
                         cudaFuncAttributeMaxDynamicSharedMemorySize, SMEM_GEMM);
    cudaFuncSetAttribute(edge_logits_kernel,
                         cudaFuncAttributeMaxDynamicSharedMemorySize, SMEM_EDGE);

    const int gblk = (NLR + 127) / 128;   // 391

    // 1: counter init (independent)
    zero_cnt_kernel<<<(NLR + 255) / 256, 256>>>();
    // 2: node projections
    gemm_dual<<<2 * gblk, 256, SMEM_GEMM>>>(left, W_l, b_l, xl,
                                            right, W_r, b_r, xr, NLR, gblk);
    // 3: degree count (independent of GEMMs)
    count_kernel<<<(ENUM + 255) / 256, 256>>>(dst);
    // 4: edge logits — profiled slot
    edge_logits_kernel<<<ENUM / 128, 256, SMEM_EDGE>>>(ef, W_e, src, dst, att);
    // 5-6: CSR scan + fill
    scan_kernel<<<1, 1024>>>();
    fill_kernel<<<(ENUM + 255) / 256, 256>>>(dst);
    // 7: warp-per-node segment softmax + message + LN
    message_ln_kernel<<<(NLR * 32 + 255) / 256, 256>>>(src, bconv, ln_g, ln_b);
    // 8-9: out MLP
    gemm128<<<gblk, 256, SMEM_GEMM>>>(ln, W1, 128, right, W1 + 128 * 128, 128,
                                      b1, h1, NLR, 1);
    gemm128<<<gblk, 256, SMEM_GEMM>>>(h1, W2, 128, nullptr, nullptr, 0,
                                      b2, out, NLR, 0);
}